// round 12
// baseline (speedup 1.0000x reference)
#include <cuda_runtime.h>
#include <math.h>

#define NUM_NODES   8192
#define MEME_DIM    64
#define VISION      2048
#define K_IN        32
#define VOCAB_N     256
#define G_TOT       (NUM_NODES * MEME_DIM)
#define TILE_F4     4096                         // float4s per tile (64*256/4)
#define GRID_P      148                          // persistent CTAs (1/SM)
#define RTHREADS    512

// Scratch (device globals; no allocation allowed)
__device__ float  d_g_raw[G_TOT];
__device__ float2 d_partials[NUM_NODES];
__device__ float  d_stats[2];  // [0]=mean, [1]=inv_std

__device__ __forceinline__ float fast_tanh(float x) {
    float r;
    asm("tanh.approx.f32 %0, %1;" : "=f"(r) : "f"(x));
    return r;
}

// ---------------------------------------------------------------------------
// Kernel 1: gather + mean (warp per node) + L2 prefetch of vocab head.
// Block b prefetches vocab bytes [b*64KB, (b+1)*64KB) -> first 64MB in L2,
// issued before the gather loads so the prefetch streams while gather stalls.
// ---------------------------------------------------------------------------
__global__ __launch_bounds__(256) void gather_kernel(
    const float* __restrict__ x,          // [2048, 64]
    const float* __restrict__ memes,      // [8192, 64]
    const int*   __restrict__ idx,        // [8192, 32]
    const float* __restrict__ vocab)      // [8192, 64, 256]
{
    const int tid  = threadIdx.x;
    // ---- L2 prefetch: 2 x 128B lines per thread = 64KB per block ----
    {
        const char* base = (const char*)vocab + (size_t)blockIdx.x * 65536;
        asm volatile("prefetch.global.L2 [%0];" :: "l"(base + tid * 128));
        asm volatile("prefetch.global.L2 [%0];" :: "l"(base + 32768 + tid * 128));
    }

    const int wid  = tid >> 5;
    const int lane = tid & 31;
    const int n    = blockIdx.x * 8 + wid;
    const int f4   = lane & 15;
    const int kh   = lane >> 4;

    const int myidx = __ldg(idx + (size_t)n * K_IN + lane);

    const float4* x4 = (const float4*)x;
    const float4* m4 = (const float4*)memes;

    float4 acc = make_float4(0.f, 0.f, 0.f, 0.f);
#pragma unroll
    for (int j = 0; j < 16; j++) {
        const int r = __shfl_sync(0xffffffffu, myidx, kh + 2 * j);
        const float4* src = (r < VISION) ? (x4 + (size_t)r * 16)
                                         : (m4 + (size_t)(r - VISION) * 16);
        const float4 v = __ldg(src + f4);
        acc.x += v.x; acc.y += v.y; acc.z += v.z; acc.w += v.w;
    }

    // pair-sum across the two k-halves (lane <-> lane^16)
    acc.x += __shfl_xor_sync(0xffffffffu, acc.x, 16);
    acc.y += __shfl_xor_sync(0xffffffffu, acc.y, 16);
    acc.z += __shfl_xor_sync(0xffffffffu, acc.z, 16);
    acc.w += __shfl_xor_sync(0xffffffffu, acc.w, 16);

    float4 g;
    g.x = acc.x * (1.f / 32.f); g.y = acc.y * (1.f / 32.f);
    g.z = acc.z * (1.f / 32.f); g.w = acc.w * (1.f / 32.f);

    if (kh == 0)
        ((float4*)(d_g_raw + (size_t)n * MEME_DIM))[f4] = g;

    float s = g.x + g.y + g.z + g.w;
    float q = g.x * g.x + g.y * g.y + g.z * g.z + g.w * g.w;
#pragma unroll
    for (int o = 8; o > 0; o >>= 1) {
        s += __shfl_down_sync(0xffffffffu, s, o, 16);
        q += __shfl_down_sync(0xffffffffu, q, o, 16);
    }
    if (lane == 0) d_partials[n] = make_float2(s, q);
}

// ---------------------------------------------------------------------------
// Kernel 2: reduce partials -> global mean / inv_std (ddof=1), deterministic
// ---------------------------------------------------------------------------
__global__ __launch_bounds__(256) void stats_kernel()
{
    __shared__ double ssum[256], ssq[256];
    const int tid = threadIdx.x;
    double s = 0.0, q = 0.0;
    for (int i = tid; i < NUM_NODES; i += 256) {
        float2 p = d_partials[i];
        s += (double)p.x;
        q += (double)p.y;
    }
    ssum[tid] = s; ssq[tid] = q;
    __syncthreads();
    for (int st = 128; st > 0; st >>= 1) {
        if (tid < st) { ssum[tid] += ssum[tid + st]; ssq[tid] += ssq[tid + st]; }
        __syncthreads();
    }
    if (tid == 0) {
        const double N = (double)G_TOT;
        double mean = ssum[0] / N;
        double var  = (ssq[0] - ssum[0] * ssum[0] / N) / (N - 1.0);
        d_stats[0] = (float)mean;
        d_stats[1] = (float)(1.0 / sqrt(var));
    }
}

// ---------------------------------------------------------------------------
// Kernel 3: fused remix, register-resident vocab, persistent 148x512.
// 2 barriers per tile; output reduction of tile i-1 deferred onto threads
// 128-383 concurrent with stats of tile i. Drain after loop.
// ---------------------------------------------------------------------------
struct RemixSmem {
    float  pd[8 * 256];    // 8KB  dot partials [ch][col]
    float  po[64 * 64];    // 16KB out partials [e][c4]
    float  fs[256];        // 1KB  fractions
    float  ws[4], wq[4], wp[4];
};

__global__ __launch_bounds__(RTHREADS, 1) void remix_kernel(
    const float* __restrict__ vocab,       // [8192, 64, 256]
    const float* __restrict__ raw_sc,      // [1]
    const float* __restrict__ raw_sh,      // [1]
    float*       __restrict__ out)         // [8192, 64]
{
    __shared__ RemixSmem sm;

    const int tid  = threadIdx.x;
    const int lane = tid & 31, w = tid >> 5;
    const int c4   = tid & 63;     // float4 column group
    const int ch   = tid >> 6;     // e-chunk 0..7

    const float sc     = __expf(__ldg(raw_sc));
    const float inv_sc = __fdividef(1.f, sc);
    const float lnsh   = __ldg(raw_sh);
    const float mean   = d_stats[0], istd = d_stats[1];

    const float4* v4 = (const float4*)vocab;

    auto reduce_prev = [&](int n_prev) {
        const int t  = tid - 128;           // 0..255
        const int eo = t >> 2;              // 0..63
        const int p4 = t & 3;               // 4 threads per e
        const float4* pr = (const float4*)(sm.po + eo * 64 + p4 * 16);
        const float4 r0 = pr[0], r1 = pr[1], r2 = pr[2], r3 = pr[3];
        float s = r0.x + r0.y + r0.z + r0.w + r1.x + r1.y + r1.z + r1.w
                + r2.x + r2.y + r2.z + r2.w + r3.x + r3.y + r3.z + r3.w;
        s += __shfl_down_sync(0xffffffffu, s, 2, 4);
        s += __shfl_down_sync(0xffffffffu, s, 1, 4);
        if (p4 == 0) out[(size_t)n_prev * MEME_DIM + eo] = s;
    };

    auto step = [&](int n, bool has_prev, float4 (&cur)[8], float4& ga, float4& gb,
                    float4 (&nxt)[8], float4& gna, float4& gnb) {
        // ---- prefetch n+GRID_P first (max latency-hiding window) ----
        const int nn = n + GRID_P;
        if (nn < NUM_NODES) {
            const float4* src = v4 + (size_t)nn * TILE_F4 + c4;
#pragma unroll
            for (int j = 0; j < 8; j++)
                nxt[j] = __ldcs(src + (ch * 8 + j) * 64);
            const float4* g4n = (const float4*)(d_g_raw + (size_t)nn * MEME_DIM);
            gna = __ldg(g4n + ch * 2);
            gnb = __ldg(g4n + ch * 2 + 1);
        }

        // standardize this tile's g
        float gr[8];
        gr[0] = (ga.x - mean) * istd; gr[1] = (ga.y - mean) * istd;
        gr[2] = (ga.z - mean) * istd; gr[3] = (ga.w - mean) * istd;
        gr[4] = (gb.x - mean) * istd; gr[5] = (gb.y - mean) * istd;
        gr[6] = (gb.z - mean) * istd; gr[7] = (gb.w - mean) * istd;

        // ---- phase B: dot partials over this thread's 8 e's ----
        {
            float4 a = make_float4(0.f, 0.f, 0.f, 0.f);
#pragma unroll
            for (int j = 0; j < 8; j++) {
                a.x = fmaf(gr[j], cur[j].x, a.x);
                a.y = fmaf(gr[j], cur[j].y, a.y);
                a.z = fmaf(gr[j], cur[j].z, a.z);
                a.w = fmaf(gr[j], cur[j].w, a.w);
            }
            ((float4*)sm.pd)[ch * 64 + c4] = a;
        }
        __syncthreads();                                   // barrier 1

        if (tid < 128) {
            // ---- stats + fractions: lane t owns cols 2t, 2t+1 ----
            const float2* pd2 = (const float2*)sm.pd;
            float d0 = 0.f, d1 = 0.f;
#pragma unroll
            for (int k = 0; k < 8; k++) {
                float2 p = pd2[k * 128 + tid];
                d0 += p.x; d1 += p.y;
            }
            float s = d0 + d1;
            float q = d0 * d0 + d1 * d1;
#pragma unroll
            for (int o = 16; o > 0; o >>= 1) {
                s += __shfl_down_sync(0xffffffffu, s, o);
                q += __shfl_down_sync(0xffffffffu, q, o);
            }
            if (lane == 0) { sm.ws[w] = s; sm.wq[w] = q; }
            asm volatile("bar.sync 8, 128;" ::: "memory");
            const float bsum = sm.ws[0] + sm.ws[1] + sm.ws[2] + sm.ws[3];
            const float bsq  = sm.wq[0] + sm.wq[1] + sm.wq[2] + sm.wq[3];

            const float m = bsum * (1.f / 256.f);
            float var = (bsq - bsum * bsum * (1.f / 256.f)) * (1.f / 255.f);
            var = fmaxf(var, 0.f);
            const float inv_sd = __fdividef(1.f, sqrtf(var) + 0.001f);

            float p0 = __expf(fast_tanh((d0 - m) * inv_sd * inv_sc) * sc * lnsh);
            float p1 = __expf(fast_tanh((d1 - m) * inv_sd * inv_sc) * sc * lnsh);

            float ps = p0 + p1;
#pragma unroll
            for (int o = 16; o > 0; o >>= 1)
                ps += __shfl_down_sync(0xffffffffu, ps, o);
            if (lane == 0) sm.wp[w] = ps;
            asm volatile("bar.sync 8, 128;" ::: "memory");
            const float psum = sm.wp[0] + sm.wp[1] + sm.wp[2] + sm.wp[3];
            const float inv_psum = __fdividef(1.f, psum + 0.001f);

            ((float2*)sm.fs)[tid] = make_float2(p0 * inv_psum, p1 * inv_psum);
        } else if (tid < 384 && has_prev) {
            // ---- concurrent: reduce + store output of tile n-GRID_P ----
            reduce_prev(n - GRID_P);
        }
        __syncthreads();                                   // barrier 2

        // ---- phase E: out partials from register-resident vocab ----
        {
            const float4 f = ((const float4*)sm.fs)[c4];
#pragma unroll
            for (int j = 0; j < 8; j++) {
                float p = cur[j].x * f.x + cur[j].y * f.y
                        + cur[j].z * f.z + cur[j].w * f.w;
                sm.po[(ch * 8 + j) * 64 + c4] = p;
            }
        }
        // no barrier: next step's barrier 1 orders po reads; drain handles last
    };

    // -------- preload tile n0 --------
    const int n0 = blockIdx.x;
    float4 bufA[8], bufB[8];
    float4 gAa, gAb, gBa, gBb;
    {
        const float4* src = v4 + (size_t)n0 * TILE_F4 + c4;
#pragma unroll
        for (int j = 0; j < 8; j++)
            bufA[j] = __ldcs(src + (ch * 8 + j) * 64);
        const float4* g4 = (const float4*)(d_g_raw + (size_t)n0 * MEME_DIM);
        gAa = __ldg(g4 + ch * 2);
        gAb = __ldg(g4 + ch * 2 + 1);
    }

    int n = n0;
    int n_last = n0;
    bool first = true;
    while (true) {
        step(n, !first, bufA, gAa, gAb, bufB, gBa, gBb);
        n_last = n; first = false;
        n += GRID_P;
        if (n >= NUM_NODES) break;
        step(n, true, bufB, gBa, gBb, bufA, gAa, gAb);
        n_last = n;
        n += GRID_P;
        if (n >= NUM_NODES) break;
    }

    // -------- drain: reduce + store the final tile's output --------
    __syncthreads();
    if (tid >= 128 && tid < 384) reduce_prev(n_last);
}

// ---------------------------------------------------------------------------
extern "C" void kernel_launch(void* const* d_in, const int* in_sizes, int n_in,
                              void* d_out, int out_size)
{
    const float* x      = (const float*)d_in[0];   // [2048, 64]
    const float* memes  = (const float*)d_in[1];   // [8192, 64]
    const int*   idx    = (const int*)  d_in[2];   // [8192, 32]
    const float* vocab  = (const float*)d_in[3];   // [8192, 64, 256]
    const float* raw_sc = (const float*)d_in[4];   // [1]
    const float* raw_sh = (const float*)d_in[5];   // [1]
    float* out = (float*)d_out;

    gather_kernel<<<NUM_NODES / 8, 256>>>(x, memes, idx, vocab);
    stats_kernel<<<1, 256>>>();
    remix_kernel<<<GRID_P, RTHREADS>>>(vocab, raw_sc, raw_sh, out);
}